// round 1
// baseline (speedup 1.0000x reference)
#include <cuda_runtime.h>
#include <math.h>

// ---------------- problem constants ----------------
#define NNODES 50000
#define NEDGES 800000
#define FIN    128
#define DH     128
#define DHL    512
#define NG     512
#define NC     512
#define POOLW  (DH + DH + DHL)   // 768

// ---------------- device scratch (allocation-free) ----------------
__device__ float g_agg[NNODES * DH];        // aggregation buffer (always 128-wide)
__device__ float g_mid[NNODES * DHL];       // gelu(agg@W1+b1)
__device__ float g_pre[NNODES * DHL];       // mid@W2+b2 (pre-BN)
__device__ float g_h1 [NNODES * DH];
__device__ float g_h2 [NNODES * DH];
__device__ float g_pool[NG * POOLW];        // [512,768] concat pooled
__device__ float g_st1[2 * DH];
__device__ float g_st2[2 * DH];
__device__ float g_st3[2 * DHL];
__device__ float g_lin1[NG * 1024];

// ---------------- helpers ----------------
__device__ __forceinline__ float gelu_f(float v) {
    return 0.5f * v * (1.0f + erff(v * 0.70710678118654752440f));
}

__device__ __forceinline__ unsigned long long dup2(float v) {
    unsigned long long r;
    unsigned u = __float_as_uint(v);
    asm("mov.b64 %0, {%1,%1};" : "=l"(r) : "r"(u));
    return r;
}

__device__ __forceinline__ void fma2(unsigned long long& acc,
                                     unsigned long long a, unsigned long long b) {
    asm("fma.rn.f32x2 %0, %1, %2, %0;" : "+l"(acc) : "l"(a), "l"(b));
}

__device__ __forceinline__ float2 unpack2(unsigned long long a) {
    unsigned lo, hi;
    asm("mov.b64 {%0,%1}, %2;" : "=r"(lo), "=r"(hi) : "l"(a));
    return make_float2(__uint_as_float(lo), __uint_as_float(hi));
}

// ---------------- generic fp32x2 GEMM: C = act(A[M,K] @ B[K,N] + bias) ----------------
// BM=64, BN=128, BK=16; 128 threads; each thread 8x8 outputs as 4x8 f32x2 pairs.
// Requires: N % 128 == 0, K % 16 == 0. M arbitrary (guarded).
// ACT: 0 = none, 1 = gelu, 2 = relu
template <int ACT>
__global__ void __launch_bounds__(128) gemm_k(
    const float* __restrict__ A, const float* __restrict__ B,
    const float* __restrict__ bias, float* __restrict__ C,
    int M, int N, int K)
{
    const int BM = 64, BN = 128, BK = 16;
    __shared__ float As[BK][BM];   // transposed: [k][m]
    __shared__ float Bs[BK][BN];

    int tid = threadIdx.x;
    int tx = tid & 15;       // 16 col-groups of 8
    int ty = tid >> 4;       // 8 row-groups of 8
    int row0 = blockIdx.y * BM + ty * 8;
    int col0 = blockIdx.x * BN + tx * 8;

    unsigned long long acc[4][8];
#pragma unroll
    for (int i = 0; i < 4; i++)
#pragma unroll
        for (int j = 0; j < 8; j++) acc[i][j] = 0ull;

    for (int kt = 0; kt < K; kt += BK) {
        // --- load A tile (64x16), transposed into As[k][m] ---
#pragma unroll
        for (int t = 0; t < 2; t++) {
            int s = tid + t * 128;          // 256 float4 slots
            int ar = s >> 2;                // row in tile
            int ak = (s & 3) << 2;          // k offset (0,4,8,12)
            int gr = blockIdx.y * BM + ar;
            float4 v = make_float4(0.f, 0.f, 0.f, 0.f);
            if (gr < M) v = *(const float4*)(A + (size_t)gr * K + kt + ak);
            As[ak + 0][ar] = v.x;
            As[ak + 1][ar] = v.y;
            As[ak + 2][ar] = v.z;
            As[ak + 3][ar] = v.w;
        }
        // --- load B tile (16x128) ---
#pragma unroll
        for (int t = 0; t < 4; t++) {
            int s = tid + t * 128;          // 512 float4 slots
            int bk = s >> 5;
            int bn = (s & 31) << 2;
            *(float4*)&Bs[bk][bn] =
                *(const float4*)(B + (size_t)(kt + bk) * N + blockIdx.x * BN + bn);
        }
        __syncthreads();

#pragma unroll
        for (int k = 0; k < BK; k++) {
            const unsigned long long* a64 =
                (const unsigned long long*)&As[k][ty * 8];
            unsigned long long a0 = a64[0], a1 = a64[1], a2 = a64[2], a3 = a64[3];
            float4 bq0 = *(const float4*)&Bs[k][tx * 8];
            float4 bq1 = *(const float4*)&Bs[k][tx * 8 + 4];
            unsigned long long bd0 = dup2(bq0.x), bd1 = dup2(bq0.y);
            unsigned long long bd2 = dup2(bq0.z), bd3 = dup2(bq0.w);
            unsigned long long bd4 = dup2(bq1.x), bd5 = dup2(bq1.y);
            unsigned long long bd6 = dup2(bq1.z), bd7 = dup2(bq1.w);
            fma2(acc[0][0], a0, bd0); fma2(acc[1][0], a1, bd0);
            fma2(acc[2][0], a2, bd0); fma2(acc[3][0], a3, bd0);
            fma2(acc[0][1], a0, bd1); fma2(acc[1][1], a1, bd1);
            fma2(acc[2][1], a2, bd1); fma2(acc[3][1], a3, bd1);
            fma2(acc[0][2], a0, bd2); fma2(acc[1][2], a1, bd2);
            fma2(acc[2][2], a2, bd2); fma2(acc[3][2], a3, bd2);
            fma2(acc[0][3], a0, bd3); fma2(acc[1][3], a1, bd3);
            fma2(acc[2][3], a2, bd3); fma2(acc[3][3], a3, bd3);
            fma2(acc[0][4], a0, bd4); fma2(acc[1][4], a1, bd4);
            fma2(acc[2][4], a2, bd4); fma2(acc[3][4], a3, bd4);
            fma2(acc[0][5], a0, bd5); fma2(acc[1][5], a1, bd5);
            fma2(acc[2][5], a2, bd5); fma2(acc[3][5], a3, bd5);
            fma2(acc[0][6], a0, bd6); fma2(acc[1][6], a1, bd6);
            fma2(acc[2][6], a2, bd6); fma2(acc[3][6], a3, bd6);
            fma2(acc[0][7], a0, bd7); fma2(acc[1][7], a1, bd7);
            fma2(acc[2][7], a2, bd7); fma2(acc[3][7], a3, bd7);
        }
        __syncthreads();
    }

    // --- epilogue ---
    float bv[8];
    *(float4*)&bv[0] = *(const float4*)(bias + col0);
    *(float4*)&bv[4] = *(const float4*)(bias + col0 + 4);

#pragma unroll
    for (int ip = 0; ip < 4; ip++) {
        float lo[8], hi[8];
#pragma unroll
        for (int j = 0; j < 8; j++) {
            float2 f = unpack2(acc[ip][j]);
            lo[j] = f.x; hi[j] = f.y;
        }
        int rbase = row0 + ip * 2;
#pragma unroll
        for (int h = 0; h < 2; h++) {
            int r = rbase + h;
            if (r < M) {
                float v[8];
#pragma unroll
                for (int j = 0; j < 8; j++) {
                    float t = (h ? hi[j] : lo[j]) + bv[j];
                    if (ACT == 1) t = gelu_f(t);
                    else if (ACT == 2) t = fmaxf(t, 0.f);
                    v[j] = t;
                }
                *(float4*)(C + (size_t)r * N + col0)     = make_float4(v[0], v[1], v[2], v[3]);
                *(float4*)(C + (size_t)r * N + col0 + 4) = make_float4(v[4], v[5], v[6], v[7]);
            }
        }
    }
}

// ---------------- misc kernels ----------------
__global__ void copy_k(const float4* __restrict__ src, float4* __restrict__ dst, int n4) {
    int i = blockIdx.x * blockDim.x + threadIdx.x;
    if (i < n4) dst[i] = src[i];
}

__global__ void zero_k(float* __restrict__ p, int n) {
    int i = blockIdx.x * blockDim.x + threadIdx.x;
    if (i < n) p[i] = 0.f;
}

// one warp per edge; 128 floats = 32 lanes x float4
__global__ void scatter_k(const float* __restrict__ xin, const int* __restrict__ src,
                          const int* __restrict__ dst, float* __restrict__ agg, int E) {
    int g = blockIdx.x * blockDim.x + threadIdx.x;
    int w = g >> 5, lane = g & 31;
    if (w >= E) return;
    int s = src[w], d = dst[w];
    float4 v = ((const float4*)(xin + (size_t)s * 128))[lane];
    float* p = agg + (size_t)d * 128 + (lane << 2);
    atomicAdd(p + 0, v.x);
    atomicAdd(p + 1, v.y);
    atomicAdd(p + 2, v.z);
    atomicAdd(p + 3, v.w);
}

// column sums + sumsq; blockDim == C (128 or 512)
__global__ void stats_k(const float* __restrict__ A, float* __restrict__ st,
                        int M, int C, int rowsPerBlock) {
    int c = threadIdx.x;
    int r0 = blockIdx.x * rowsPerBlock;
    int r1 = min(r0 + rowsPerBlock, M);
    float s = 0.f, q = 0.f;
    for (int r = r0; r < r1; r++) {
        float v = A[(size_t)r * C + c];
        s += v;
        q = fmaf(v, v, q);
    }
    atomicAdd(&st[c], s);
    atomicAdd(&st[C + c], q);
}

// convert (sum, sumsq) -> (scale, shift) in place
__global__ void bnfin_k(float* __restrict__ st, const float* __restrict__ g,
                        const float* __restrict__ b, int C, float invN) {
    int c = blockIdx.x * blockDim.x + threadIdx.x;
    if (c >= C) return;
    float mu  = st[c] * invN;
    float var = st[C + c] * invN - mu * mu;
    float sc  = g[c] * rsqrtf(var + 1e-5f);
    st[c]     = sc;
    st[C + c] = b[c] - mu * sc;
}

// h = gelu(pre*scale + shift); optional store of h; pooled[batch[r]] += h
__global__ void bnpool_k(const float* __restrict__ pre, const float* __restrict__ st,
                         const int* __restrict__ batch, float* __restrict__ hout,
                         float* __restrict__ pool, int M, int C, int poolOff) {
    int i = blockIdx.x * blockDim.x + threadIdx.x;
    int c4cnt = C >> 2;
    int r = i / c4cnt;
    if (r >= M) return;
    int c = (i - r * c4cnt) << 2;
    float4 v  = *(const float4*)(pre + (size_t)r * C + c);
    float4 sc = *(const float4*)(st + c);
    float4 sh = *(const float4*)(st + C + c);
    float o0 = gelu_f(fmaf(v.x, sc.x, sh.x));
    float o1 = gelu_f(fmaf(v.y, sc.y, sh.y));
    float o2 = gelu_f(fmaf(v.z, sc.z, sh.z));
    float o3 = gelu_f(fmaf(v.w, sc.w, sh.w));
    if (hout) *(float4*)(hout + (size_t)r * C + c) = make_float4(o0, o1, o2, o3);
    int gidx = batch[r];
    float* p = pool + (size_t)gidx * POOLW + poolOff + c;
    atomicAdd(p + 0, o0);
    atomicAdd(p + 1, o1);
    atomicAdd(p + 2, o2);
    atomicAdd(p + 3, o3);
}

// ---------------- launch ----------------
static inline void launch_gemm(const float* A, const float* B, const float* bias,
                               float* C, int M, int N, int K, int act) {
    dim3 grid(N / 128, (M + 63) / 64);
    if (act == 1)      gemm_k<1><<<grid, 128>>>(A, B, bias, C, M, N, K);
    else if (act == 2) gemm_k<2><<<grid, 128>>>(A, B, bias, C, M, N, K);
    else               gemm_k<0><<<grid, 128>>>(A, B, bias, C, M, N, K);
}

extern "C" void kernel_launch(void* const* d_in, const int* in_sizes, int n_in,
                              void* d_out, int out_size) {
    const float* x     = (const float*)d_in[0];
    const int*   ei    = (const int*)d_in[1];
    const int*   batch = (const int*)d_in[2];
    const float* c1W1 = (const float*)d_in[3];
    const float* c1b1 = (const float*)d_in[4];
    const float* c1W2 = (const float*)d_in[5];
    const float* c1b2 = (const float*)d_in[6];
    const float* bn1g = (const float*)d_in[7];
    const float* bn1b = (const float*)d_in[8];
    const float* c2W1 = (const float*)d_in[9];
    const float* c2b1 = (const float*)d_in[10];
    const float* c2W2 = (const float*)d_in[11];
    const float* c2b2 = (const float*)d_in[12];
    const float* bn2g = (const float*)d_in[13];
    const float* bn2b = (const float*)d_in[14];
    const float* c3W1 = (const float*)d_in[15];
    const float* c3b1 = (const float*)d_in[16];
    const float* c3W2 = (const float*)d_in[17];
    const float* c3b2 = (const float*)d_in[18];
    const float* bn3g = (const float*)d_in[19];
    const float* bn3b = (const float*)d_in[20];
    const float* l1W  = (const float*)d_in[21];
    const float* l1b  = (const float*)d_in[22];
    const float* l2W  = (const float*)d_in[23];
    const float* l2b  = (const float*)d_in[24];
    float* out = (float*)d_out;

    const int* srcp = ei;
    const int* dstp = ei + NEDGES;

    float *agg, *mid, *pre, *h1, *h2, *pool, *s1, *s2, *s3, *lin1;
    cudaGetSymbolAddress((void**)&agg,  g_agg);
    cudaGetSymbolAddress((void**)&mid,  g_mid);
    cudaGetSymbolAddress((void**)&pre,  g_pre);
    cudaGetSymbolAddress((void**)&h1,   g_h1);
    cudaGetSymbolAddress((void**)&h2,   g_h2);
    cudaGetSymbolAddress((void**)&pool, g_pool);
    cudaGetSymbolAddress((void**)&s1,   g_st1);
    cudaGetSymbolAddress((void**)&s2,   g_st2);
    cudaGetSymbolAddress((void**)&s3,   g_st3);
    cudaGetSymbolAddress((void**)&lin1, g_lin1);

    const float invN = 1.0f / (float)NNODES;
    const int n4_128 = NNODES * DH / 4;           // 1.6M float4
    const int copyBlocks = (n4_128 + 255) / 256;
    const int scatterBlocks = NEDGES / 8;         // 256 thr = 8 warps, exact
    const int statsBlocks = (NNODES + 255) / 256; // rowsPerBlock = 256
    const int bn128Blocks = (NNODES * DH / 4 + 255) / 256;
    const int bn512Blocks = (NNODES * DHL / 4 + 255) / 256;

    // zero pooled + stats accumulators
    zero_k<<<(NG * POOLW + 255) / 256, 256>>>(pool, NG * POOLW);
    zero_k<<<1, 256>>>(s1, 2 * DH);
    zero_k<<<1, 256>>>(s2, 2 * DH);
    zero_k<<<4, 256>>>(s3, 2 * DHL);

    // -------- layer 1 --------
    copy_k<<<copyBlocks, 256>>>((const float4*)x, (float4*)agg, n4_128);
    scatter_k<<<scatterBlocks, 256>>>(x, srcp, dstp, agg, NEDGES);
    launch_gemm(agg, c1W1, c1b1, mid, NNODES, DH, DH, 1);   // gelu
    launch_gemm(mid, c1W2, c1b2, pre, NNODES, DH, DH, 0);
    stats_k<<<statsBlocks, DH>>>(pre, s1, NNODES, DH, 256);
    bnfin_k<<<1, DH>>>(s1, bn1g, bn1b, DH, invN);
    bnpool_k<<<bn128Blocks, 256>>>(pre, s1, batch, h1, pool, NNODES, DH, 0);

    // -------- layer 2 --------
    copy_k<<<copyBlocks, 256>>>((const float4*)h1, (float4*)agg, n4_128);
    scatter_k<<<scatterBlocks, 256>>>(h1, srcp, dstp, agg, NEDGES);
    launch_gemm(agg, c2W1, c2b1, mid, NNODES, DH, DH, 1);
    launch_gemm(mid, c2W2, c2b2, pre, NNODES, DH, DH, 0);
    stats_k<<<statsBlocks, DH>>>(pre, s2, NNODES, DH, 256);
    bnfin_k<<<1, DH>>>(s2, bn2g, bn2b, DH, invN);
    bnpool_k<<<bn128Blocks, 256>>>(pre, s2, batch, h2, pool, NNODES, DH, DH);

    // -------- layer 3 --------
    copy_k<<<copyBlocks, 256>>>((const float4*)h2, (float4*)agg, n4_128);
    scatter_k<<<scatterBlocks, 256>>>(h2, srcp, dstp, agg, NEDGES);
    launch_gemm(agg, c3W1, c3b1, mid, NNODES, DHL, DH, 1);
    launch_gemm(mid, c3W2, c3b2, pre, NNODES, DHL, DHL, 0);
    stats_k<<<statsBlocks, DHL>>>(pre, s3, NNODES, DHL, 256);
    bnfin_k<<<1, DHL>>>(s3, bn3g, bn3b, DHL, invN);
    bnpool_k<<<bn512Blocks, 256>>>(pre, s3, batch, nullptr, pool, NNODES, DHL, 2 * DH);

    // -------- head --------
    launch_gemm(pool, l1W, l1b, lin1, NG, 1024, POOLW, 2);  // relu
    launch_gemm(lin1, l2W, l2b, out, NG, NC, 1024, 0);
}

// round 4
// speedup vs baseline: 1.2787x; 1.2787x over previous
#include <cuda_runtime.h>
#include <cuda_bf16.h>
#include <math.h>
#include <stdint.h>

// ---------------- problem constants ----------------
#define NNODES 50000
#define MPAD   50048          // 391 * 128
#define NEDGES 800000
#define DH     128
#define DHL    512
#define NG     512
#define NC     512
#define POOLW  (DH + DH + DHL)   // 768

// ---------------- device scratch (allocation-free) ----------------
__device__ float g_agg[NNODES * DH];
__device__ float g_pre[NNODES * DHL];
__device__ float g_h1 [NNODES * DH];
__device__ float g_h2 [NNODES * DH];
__device__ float g_pool[NG * POOLW];
__device__ float g_st1[2 * DH];
__device__ float g_st2[2 * DH];
__device__ float g_st3[2 * DHL];

// bf16 split operand buffers
__device__ __nv_bfloat16 g_sa_h[MPAD * 768];
__device__ __nv_bfloat16 g_sa_l[MPAD * 768];
__device__ __nv_bfloat16 g_sm_h[MPAD * 1024];
__device__ __nv_bfloat16 g_sm_l[MPAD * 1024];

// weights (transposed to [N,K], split)
#define OFF_C1W1 0
#define OFF_C1W2 16384
#define OFF_C2W1 32768
#define OFF_C2W2 49152
#define OFF_C3W1 65536
#define OFF_C3W2 131072
#define OFF_L1W  393216
#define OFF_L2W  1179648
#define WTOT     1703936
__device__ __nv_bfloat16 g_w_h[WTOT];
__device__ __nv_bfloat16 g_w_l[WTOT];

// ---------------- helpers ----------------
__device__ __forceinline__ float gelu_f(float v) {
    return 0.5f * v * (1.0f + erff(v * 0.70710678118654752440f));
}

__device__ __forceinline__ uint32_t s2u(const void* p) {
    uint32_t a;
    asm("{ .reg .u64 t; cvta.to.shared.u64 t, %1; cvt.u32.u64 %0, t; }"
        : "=r"(a) : "l"(p));
    return a;
}

__device__ __forceinline__ void cpasync16(uint32_t saddr, const void* gaddr) {
    asm volatile("cp.async.ca.shared.global [%0], [%1], 16;"
                 :: "r"(saddr), "l"(gaddr));
}

__device__ __forceinline__ void cp_commit() {
    asm volatile("cp.async.commit_group;");
}

template <int N>
__device__ __forceinline__ void cp_wait() {
    asm volatile("cp.async.wait_group %0;" :: "n"(N));
}

__device__ __forceinline__ void ldsm_x4(uint32_t addr, uint32_t& r0, uint32_t& r1,
                                        uint32_t& r2, uint32_t& r3) {
    asm volatile("ldmatrix.sync.aligned.m8n8.x4.shared.b16 {%0,%1,%2,%3}, [%4];"
                 : "=r"(r0), "=r"(r1), "=r"(r2), "=r"(r3) : "r"(addr));
}

__device__ __forceinline__ void mma_bf16(float* c, const uint32_t* a, const uint32_t* b) {
    asm volatile(
        "mma.sync.aligned.m16n8k16.row.col.f32.bf16.bf16.f32 "
        "{%0,%1,%2,%3}, {%4,%5,%6,%7}, {%8,%9}, {%0,%1,%2,%3};"
        : "+f"(c[0]), "+f"(c[1]), "+f"(c[2]), "+f"(c[3])
        : "r"(a[0]), "r"(a[1]), "r"(a[2]), "r"(a[3]), "r"(b[0]), "r"(b[1]));
}

// ---------------- mma.sync GEMM: C = act(A[M,K] @ Bt[N,K]^T + bias) ----------------
// A, Bt given as bf16 hi/lo splits. Computes Ah*Bh + Ah*Bl + Al*Bh (fp32 acc).
// CTA tile 128x128, BK=32, 8 warps (4m x 2n), warp tile 32x64, 4-stage cp.async.
// ACT: 0 none, 1 gelu, 2 relu. OSPLIT: 0 -> fp32 Cf, 1 -> bf16 split Oh/Ol.
#define STG_A     10240           // 128 rows * 80B
#define STG_TOT   20480           // A + B
#define NSTAGE    4
#define SMEM_SZ   (NSTAGE * STG_TOT)

template <int ACT, int OSPLIT>
__global__ void __launch_bounds__(256, 2) mmagemm_k(
    const __nv_bfloat16* __restrict__ Ah, const __nv_bfloat16* __restrict__ Al,
    const __nv_bfloat16* __restrict__ Bh, const __nv_bfloat16* __restrict__ Bl,
    const float* __restrict__ bias,
    float* __restrict__ Cf,
    __nv_bfloat16* __restrict__ Oh, __nv_bfloat16* __restrict__ Ol,
    int M, int N, int K)
{
    extern __shared__ char smem[];
    const uint32_t sbase = s2u(smem);
    const int tid = threadIdx.x;
    const int w = tid >> 5, lane = tid & 31;
    const int wm = w & 3, wn = w >> 2;
    const int row0 = blockIdx.y * 128, col0 = blockIdx.x * 128;
    const int kc = K >> 5;            // 32-wide chunks per pass
    const int nc = 3 * kc;

    float acc[2][8][4];
#pragma unroll
    for (int i = 0; i < 2; i++)
#pragma unroll
        for (int j = 0; j < 8; j++)
#pragma unroll
            for (int q = 0; q < 4; q++) acc[i][j][q] = 0.f;

    // ---- async load of chunk c into stage s ----
    auto load_chunk = [&](int c, int s) {
        int p = c / kc;
        int k0 = (c - p * kc) << 5;
        const __nv_bfloat16* Ab = (p == 2) ? Al : Ah;
        const __nv_bfloat16* Bb = (p == 1) ? Bl : Bh;
        uint32_t As = sbase + s * STG_TOT;
        uint32_t Bs = As + STG_A;
#pragma unroll
        for (int t = 0; t < 2; t++) {
            int si = tid + t * 256;       // 0..511
            int r = si >> 2, cc = si & 3;
            int gr = min(row0 + r, M - 1);
            cpasync16(As + r * 80 + cc * 16,
                      Ab + (size_t)gr * K + k0 + cc * 8);
            cpasync16(Bs + r * 80 + cc * 16,
                      Bb + (size_t)(col0 + r) * K + k0 + cc * 8);
        }
    };

    // preload
    for (int s = 0; s < NSTAGE - 1; s++) {
        if (s < nc) load_chunk(s, s);
        cp_commit();
    }

    for (int c = 0; c < nc; c++) {
        cp_wait<NSTAGE - 2>();
        __syncthreads();

        int st = c & (NSTAGE - 1);
        uint32_t As = sbase + st * STG_TOT;
        uint32_t Bs = As + STG_A;

#pragma unroll
        for (int ko = 0; ko < 2; ko++) {
            uint32_t af[2][4];
#pragma unroll
            for (int mt = 0; mt < 2; mt++) {
                uint32_t addr = As + (wm * 32 + mt * 16 + (lane & 15)) * 80
                                + ko * 32 + ((lane >> 4) << 4);
                ldsm_x4(addr, af[mt][0], af[mt][1], af[mt][2], af[mt][3]);
            }
            uint32_t bf[8][2];
#pragma unroll
            for (int g = 0; g < 4; g++) {
                uint32_t nrow = wn * 64 + g * 16 + (lane & 7) + ((lane >> 4) << 3);
                uint32_t kb = ko * 32 + (((lane >> 3) & 1) << 4);
                uint32_t r0, r1, r2, r3;
                ldsm_x4(Bs + nrow * 80 + kb, r0, r1, r2, r3);
                bf[2 * g][0] = r0; bf[2 * g][1] = r1;
                bf[2 * g + 1][0] = r2; bf[2 * g + 1][1] = r3;
            }
#pragma unroll
            for (int mt = 0; mt < 2; mt++)
#pragma unroll
                for (int j = 0; j < 8; j++)
                    mma_bf16(acc[mt][j], af[mt], bf[j]);
        }
        __syncthreads();
        if (c + NSTAGE - 1 < nc)
            load_chunk(c + NSTAGE - 1, (c + NSTAGE - 1) & (NSTAGE - 1));
        cp_commit();
    }

    // ---- epilogue ----
    const int quad = lane >> 2, qlane = lane & 3;
#pragma unroll
    for (int mt = 0; mt < 2; mt++) {
#pragma unroll
        for (int half = 0; half < 2; half++) {
            int r = row0 + wm * 32 + mt * 16 + quad + half * 8;
            if (r >= M) continue;
#pragma unroll
            for (int j = 0; j < 8; j++) {
                int cidx = col0 + wn * 64 + j * 8 + qlane * 2;
                float v0 = acc[mt][j][2 * half]     + bias[cidx];
                float v1 = acc[mt][j][2 * half + 1] + bias[cidx + 1];
                if (ACT == 1) { v0 = gelu_f(v0); v1 = gelu_f(v1); }
                else if (ACT == 2) { v0 = fmaxf(v0, 0.f); v1 = fmaxf(v1, 0.f); }
                if (OSPLIT) {
                    __nv_bfloat16 h0 = __float2bfloat16(v0);
                    __nv_bfloat16 h1 = __float2bfloat16(v1);
                    __nv_bfloat16 l0 = __float2bfloat16(v0 - __bfloat162float(h0));
                    __nv_bfloat16 l1 = __float2bfloat16(v1 - __bfloat162float(h1));
                    *(__nv_bfloat162*)(Oh + (size_t)r * N + cidx) =
                        __halves2bfloat162(h0, h1);
                    *(__nv_bfloat162*)(Ol + (size_t)r * N + cidx) =
                        __halves2bfloat162(l0, l1);
                } else {
                    *(float2*)(Cf + (size_t)r * N + cidx) = make_float2(v0, v1);
                }
            }
        }
    }
}

// ---------------- split / transpose-split ----------------
__global__ void split_k(const float4* __restrict__ in,
                        __nv_bfloat162* __restrict__ hi,
                        __nv_bfloat162* __restrict__ lo, int n4) {
    int i = blockIdx.x * blockDim.x + threadIdx.x;
    if (i >= n4) return;
    float4 v = in[i];
    __nv_bfloat16 hx = __float2bfloat16(v.x), hy = __float2bfloat16(v.y);
    __nv_bfloat16 hz = __float2bfloat16(v.z), hw = __float2bfloat16(v.w);
    hi[2 * i]     = __halves2bfloat162(hx, hy);
    hi[2 * i + 1] = __halves2bfloat162(hz, hw);
    lo[2 * i]     = __halves2bfloat162(
        __float2bfloat16(v.x - __bfloat162float(hx)),
        __float2bfloat16(v.y - __bfloat162float(hy)));
    lo[2 * i + 1] = __halves2bfloat162(
        __float2bfloat16(v.z - __bfloat162float(hz)),
        __float2bfloat16(v.w - __bfloat162float(hw)));
}

__global__ void splitT_k(const float* __restrict__ B,
                         __nv_bfloat16* __restrict__ th,
                         __nv_bfloat16* __restrict__ tl, int K, int N) {
    int idx = blockIdx.x * blockDim.x + threadIdx.x;
    if (idx >= K * N) return;
    int k = idx / N, n = idx - k * N;
    float v = B[idx];
    __nv_bfloat16 h = __float2bfloat16(v);
    th[(size_t)n * K + k] = h;
    tl[(size_t)n * K + k] = __float2bfloat16(v - __bfloat162float(h));
}

// ---------------- misc kernels ----------------
__global__ void copy_k(const float4* __restrict__ src, float4* __restrict__ dst, int n4) {
    int i = blockIdx.x * blockDim.x + threadIdx.x;
    if (i < n4) dst[i] = src[i];
}

__global__ void zero_k(float* __restrict__ p, int n) {
    int i = blockIdx.x * blockDim.x + threadIdx.x;
    if (i < n) p[i] = 0.f;
}

__global__ void scatter_k(const float* __restrict__ xin, const int* __restrict__ src,
                          const int* __restrict__ dst, float* __restrict__ agg, int E) {
    int g = blockIdx.x * blockDim.x + threadIdx.x;
    int w = g >> 5, lane = g & 31;
    if (w >= E) return;
    int s = src[w], d = dst[w];
    float4 v = ((const float4*)(xin + (size_t)s * 128))[lane];
    float* p = agg + (size_t)d * 128 + (lane << 2);
    atomicAdd(p + 0, v.x);
    atomicAdd(p + 1, v.y);
    atomicAdd(p + 2, v.z);
    atomicAdd(p + 3, v.w);
}

__global__ void stats_k(const float* __restrict__ A, float* __restrict__ st,
                        int M, int C, int rowsPerBlock) {
    int c = threadIdx.x;
    int r0 = blockIdx.x * rowsPerBlock;
    int r1 = min(r0 + rowsPerBlock, M);
    float s = 0.f, q = 0.f;
    for (int r = r0; r < r1; r++) {
        float v = A[(size_t)r * C + c];
        s += v;
        q = fmaf(v, v, q);
    }
    atomicAdd(&st[c], s);
    atomicAdd(&st[C + c], q);
}

__global__ void bnfin_k(float* __restrict__ st, const float* __restrict__ g,
                        const float* __restrict__ b, int C, float invN) {
    int c = blockIdx.x * blockDim.x + threadIdx.x;
    if (c >= C) return;
    float mu  = st[c] * invN;
    float var = st[C + c] * invN - mu * mu;
    float sc  = g[c] * rsqrtf(var + 1e-5f);
    st[c]     = sc;
    st[C + c] = b[c] - mu * sc;
}

__global__ void bnpool_k(const float* __restrict__ pre, const float* __restrict__ st,
                         const int* __restrict__ batch, float* __restrict__ hout,
                         float* __restrict__ pool, int M, int C, int poolOff) {
    int i = blockIdx.x * blockDim.x + threadIdx.x;
    int c4cnt = C >> 2;
    int r = i / c4cnt;
    if (r >= M) return;
    int c = (i - r * c4cnt) << 2;
    float4 v  = *(const float4*)(pre + (size_t)r * C + c);
    float4 sc = *(const float4*)(st + c);
    float4 sh = *(const float4*)(st + C + c);
    float o0 = gelu_f(fmaf(v.x, sc.x, sh.x));
    float o1 = gelu_f(fmaf(v.y, sc.y, sh.y));
    float o2 = gelu_f(fmaf(v.z, sc.z, sh.z));
    float o3 = gelu_f(fmaf(v.w, sc.w, sh.w));
    if (hout) *(float4*)(hout + (size_t)r * C + c) = make_float4(o0, o1, o2, o3);
    int gidx = batch[r];
    float* p = pool + (size_t)gidx * POOLW + poolOff + c;
    atomicAdd(p + 0, o0);
    atomicAdd(p + 1, o1);
    atomicAdd(p + 2, o2);
    atomicAdd(p + 3, o3);
}

// ---------------- host launch ----------------
template <int ACT, int OSPLIT>
static void run_gemm(const __nv_bfloat16* Ah, const __nv_bfloat16* Al,
                     const __nv_bfloat16* Bh, const __nv_bfloat16* Bl,
                     const float* bias, float* Cf,
                     __nv_bfloat16* Oh, __nv_bfloat16* Ol,
                     int M, int N, int K) {
    cudaFuncSetAttribute(mmagemm_k<ACT, OSPLIT>,
                         cudaFuncAttributeMaxDynamicSharedMemorySize, SMEM_SZ);
    dim3 grid(N / 128, (M + 127) / 128);
    mmagemm_k<ACT, OSPLIT><<<grid, 256, SMEM_SZ>>>(Ah, Al, Bh, Bl, bias, Cf,
                                                   Oh, Ol, M, N, K);
}

extern "C" void kernel_launch(void* const* d_in, const int* in_sizes, int n_in,
                              void* d_out, int out_size) {
    const float* x     = (const float*)d_in[0];
    const int*   ei    = (const int*)d_in[1];
    const int*   batch = (const int*)d_in[2];
    const float* c1W1 = (const float*)d_in[3];
    const float* c1b1 = (const float*)d_in[4];
    const float* c1W2 = (const float*)d_in[5];
    const float* c1b2 = (const float*)d_in[6];
    const float* bn1g = (const float*)d_in[7];
    const float* bn1b = (const float*)d_in[8];
    const float* c2W1 = (const float*)d_in[9];
    const float* c2b1 = (const float*)d_in[10];
    const float* c2W2 = (const float*)d_in[11];
    const float* c2b2 = (const float*)d_in[12];
    const float* bn2g = (const float*)d_in[13];
    const float* bn2b = (const float*)d_in[14];
    const float* c3W1 = (const float*)d_in[15];
    const float* c3b1 = (const float*)d_in[16];
    const float* c3W2 = (const float*)d_in[17];
    const float* c3b2 = (const float*)d_in[18];
    const float* bn3g = (const float*)d_in[19];
    const float* bn3b = (const float*)d_in[20];
    const float* l1W  = (const float*)d_in[21];
    const float* l1b  = (const float*)d_in[22];
    const float* l2W  = (const float*)d_in[23];
    const float* l2b  = (const float*)d_in[24];
    float* out = (float*)d_out;

    const int* srcp = ei;
    const int* dstp = ei + NEDGES;

    float *agg, *pre, *h1, *h2, *pool, *s1, *s2, *s3;
    __nv_bfloat16 *sah, *sal, *smh, *sml, *wh, *wl;
    cudaGetSymbolAddress((void**)&agg,  g_agg);
    cudaGetSymbolAddress((void**)&pre,  g_pre);
    cudaGetSymbolAddress((void**)&h1,   g_h1);
    cudaGetSymbolAddress((void**)&h2,   g_h2);
    cudaGetSymbolAddress((void**)&pool, g_pool);
    cudaGetSymbolAddress((void**)&s1,   g_st1);
    cudaGetSymbolAddress((void**)&s2,   g_st2);
    cudaGetSymbolAddress((void**)&s3,   g_st3);
    cudaGetSymbolAddress((void**)&sah,  g_sa_h);
    cudaGetSymbolAddress((void**)&sal,  g_sa_l);
    cudaGetSymbolAddress((void**)&smh,  g_sm_h);
    cudaGetSymbolAddress((void**)&sml,  g_sm_l);
    cudaGetSymbolAddress((void**)&wh,   g_w_h);
    cudaGetSymbolAddress((void**)&wl,   g_w_l);

    const float invN = 1.0f / (float)NNODES;
    const int n4_128 = NNODES * DH / 4;
    const int copyBlocks = (n4_128 + 255) / 256;
    const int scatterBlocks = NEDGES / 8;
    const int statsBlocks = (NNODES + 255) / 256;
    const int bn128Blocks = (NNODES * DH / 4 + 255) / 256;
    const int bn512Blocks = (NNODES * DHL / 4 + 255) / 256;
    const int splitAggBlocks = (n4_128 + 255) / 256;

    // zero pooled + stats accumulators
    zero_k<<<(NG * POOLW + 255) / 256, 256>>>(pool, NG * POOLW);
    zero_k<<<1, 256>>>(s1, 2 * DH);
    zero_k<<<1, 256>>>(s2, 2 * DH);
    zero_k<<<4, 256>>>(s3, 2 * DHL);

    // split+transpose all weights to [N,K] bf16 hi/lo
    splitT_k<<<(128 * 128 + 255) / 256, 256>>>(c1W1, wh + OFF_C1W1, wl + OFF_C1W1, 128, 128);
    splitT_k<<<(128 * 128 + 255) / 256, 256>>>(c1W2, wh + OFF_C1W2, wl + OFF_C1W2, 128, 128);
    splitT_k<<<(128 * 128 + 255) / 256, 256>>>(c2W1, wh + OFF_C2W1, wl + OFF_C2W1, 128, 128);
    splitT_k<<<(128 * 128 + 255) / 256, 256>>>(c2W2, wh + OFF_C2W2, wl + OFF_C2W2, 128, 128);
    splitT_k<<<(128 * 512 + 255) / 256, 256>>>(c3W1, wh + OFF_C3W1, wl + OFF_C3W1, 128, 512);
    splitT_k<<<(512 * 512 + 255) / 256, 256>>>(c3W2, wh + OFF_C3W2, wl + OFF_C3W2, 512, 512);
    splitT_k<<<(768 * 1024 + 255) / 256, 256>>>(l1W, wh + OFF_L1W, wl + OFF_L1W, 768, 1024);
    splitT_k<<<(1024 * 512 + 255) / 256, 256>>>(l2W, wh + OFF_L2W, wl + OFF_L2W, 1024, 512);

    // -------- layer 1 --------
    copy_k<<<copyBlocks, 256>>>((const float4*)x, (float4*)agg, n4_128);
    scatter_k<<<scatterBlocks, 256>>>(x, srcp, dstp, agg, NEDGES);
    split_k<<<splitAggBlocks, 256>>>((const float4*)agg, (__nv_bfloat162*)sah,
                                     (__nv_bfloat162*)sal, n4_128);
    run_gemm<1, 1>(sah, sal, wh + OFF_C1W1, wl + OFF_C1W1, c1b1,
                   nullptr, smh, sml, NNODES, DH, DH);
    run_gemm<0, 0>(smh, sml, wh + OFF_C1W2, wl + OFF_C1W2, c1b2,
                   pre, nullptr, nullptr, NNODES, DH, DH);
    stats_k<<<statsBlocks, DH>>>(pre, s1, NNODES, DH, 256);
    bnfin_k<<<1, DH>>>(s1, bn1g, bn1b, DH, invN);
    bnpool_k<<<bn128Blocks, 256>>>(pre, s1, batch, h1, pool, NNODES, DH, 0);

    // -------- layer 2 --------
    copy_k<<<copyBlocks, 256>>>((const float4*)h1, (float4*)agg, n4_128);
    scatter_k<<<scatterBlocks, 256>>>(h1, srcp, dstp, agg, NEDGES);
    split_k<<<splitAggBlocks, 256>>>((const float4*)agg, (__nv_bfloat162*)sah,
                                     (__nv_bfloat162*)sal, n4_128);
    run_gemm<1, 1>(sah, sal, wh + OFF_C2W1, wl + OFF_C2W1, c2b1,
                   nullptr, smh, sml, NNODES, DH, DH);
    run_gemm<0, 0>(smh, sml, wh + OFF_C2W2, wl + OFF_C2W2, c2b2,
                   pre, nullptr, nullptr, NNODES, DH, DH);
    stats_k<<<statsBlocks, DH>>>(pre, s2, NNODES, DH, 256);
    bnfin_k<<<1, DH>>>(s2, bn2g, bn2b, DH, invN);
    bnpool_k<<<bn128Blocks, 256>>>(pre, s2, batch, h2, pool, NNODES, DH, DH);

    // -------- layer 3 --------
    copy_k<<<copyBlocks, 256>>>((const float4*)h2, (float4*)agg, n4_128);
    scatter_k<<<scatterBlocks, 256>>>(h2, srcp, dstp, agg, NEDGES);
    split_k<<<splitAggBlocks, 256>>>((const float4*)agg, (__nv_bfloat162*)sah,
                                     (__nv_bfloat162*)sal, n4_128);
    run_gemm<1, 1>(sah, sal, wh + OFF_C3W1, wl + OFF_C3W1, c3b1,
                   nullptr, smh, sml, NNODES, DHL, DH);
    run_gemm<0, 0>(smh, sml, wh + OFF_C3W2, wl + OFF_C3W2, c3b2,
                   pre, nullptr, nullptr, NNODES, DHL, DHL);
    stats_k<<<statsBlocks, DHL>>>(pre, s3, NNODES, DHL, 256);
    bnfin_k<<<1, DHL>>>(s3, bn3g, bn3b, DHL, invN);
    bnpool_k<<<bn512Blocks, 256>>>(pre, s3, batch, nullptr, pool, NNODES, DHL, 2 * DH);

    // -------- head --------
    split_k<<<(NG * POOLW / 4 + 255) / 256, 256>>>((const float4*)pool,
                                                   (__nv_bfloat162*)sah,
                                                   (__nv_bfloat162*)sal, NG * POOLW / 4);
    run_gemm<2, 1>(sah, sal, wh + OFF_L1W, wl + OFF_L1W, l1b,
                   nullptr, smh, sml, NG, 1024, POOLW);
    run_gemm<0, 0>(smh, sml, wh + OFF_L2W, wl + OFF_L2W, l2b,
                   out, nullptr, nullptr, NG, NC, 1024);
}

// round 6
// speedup vs baseline: 1.9230x; 1.5039x over previous
#include <cuda_runtime.h>
#include <cuda_bf16.h>
#include <math.h>
#include <stdint.h>

// ---------------- problem constants ----------------
#define NNODES 50000
#define MPAD   50048
#define NEDGES 800000
#define DH     128
#define DHL    512
#define NG     512
#define NC     512
#define POOLW  (DH + DH + DHL)   // 768

// ---------------- device scratch (allocation-free) ----------------
__device__ float g_pre[NNODES * DHL];
__device__ float g_h1 [NNODES * DH];
__device__ float g_h2 [NNODES * DH];
__device__ float g_pool[NG * POOLW];
__device__ float g_st1[2 * DH];
__device__ float g_st2[2 * DH];
__device__ float g_st3[2 * DHL];

// CSR scratch
__device__ int g_deg[NNODES];
__device__ int g_rowptr[NNODES];
__device__ int g_cur[NNODES];
__device__ int g_eidx[NEDGES];
__device__ int g_bsum[256];

// bf16 split operand buffers
__device__ __nv_bfloat16 g_sa_h[MPAD * 768];
__device__ __nv_bfloat16 g_sa_l[MPAD * 768];
__device__ __nv_bfloat16 g_sm_h[MPAD * 1024];
__device__ __nv_bfloat16 g_sm_l[MPAD * 1024];

// weights (transposed to [N,K], split)
#define OFF_C1W1 0
#define OFF_C1W2 16384
#define OFF_C2W1 32768
#define OFF_C2W2 49152
#define OFF_C3W1 65536
#define OFF_C3W2 131072
#define OFF_L1W  393216
#define OFF_L2W  1179648
#define WTOT     1703936
__device__ __nv_bfloat16 g_w_h[WTOT];
__device__ __nv_bfloat16 g_w_l[WTOT];

// ---------------- helpers ----------------
__device__ __forceinline__ float gelu_f(float v) {
    return 0.5f * v * (1.0f + erff(v * 0.70710678118654752440f));
}

__device__ __forceinline__ uint32_t s2u(const void* p) {
    uint32_t a;
    asm("{ .reg .u64 t; cvta.to.shared.u64 t, %1; cvt.u32.u64 %0, t; }"
        : "=r"(a) : "l"(p));
    return a;
}

__device__ __forceinline__ void cpasync16(uint32_t saddr, const void* gaddr) {
    asm volatile("cp.async.ca.shared.global [%0], [%1], 16;"
                 :: "r"(saddr), "l"(gaddr));
}

__device__ __forceinline__ void cp_commit() {
    asm volatile("cp.async.commit_group;");
}

template <int N>
__device__ __forceinline__ void cp_wait() {
    asm volatile("cp.async.wait_group %0;" :: "n"(N));
}

__device__ __forceinline__ void ldsm_x4(uint32_t addr, uint32_t& r0, uint32_t& r1,
                                        uint32_t& r2, uint32_t& r3) {
    asm volatile("ldmatrix.sync.aligned.m8n8.x4.shared.b16 {%0,%1,%2,%3}, [%4];"
                 : "=r"(r0), "=r"(r1), "=r"(r2), "=r"(r3) : "r"(addr));
}

__device__ __forceinline__ void mma_bf16(float* c, const uint32_t* a, const uint32_t* b) {
    asm volatile(
        "mma.sync.aligned.m16n8k16.row.col.f32.bf16.bf16.f32 "
        "{%0,%1,%2,%3}, {%4,%5,%6,%7}, {%8,%9}, {%0,%1,%2,%3};"
        : "+f"(c[0]), "+f"(c[1]), "+f"(c[2]), "+f"(c[3])
        : "r"(a[0]), "r"(a[1]), "r"(a[2]), "r"(a[3]), "r"(b[0]), "r"(b[1]));
}

// ---------------- mma.sync GEMM ----------------
#define STG_A     10240
#define STG_TOT   20480
#define NSTAGE    4
#define SMEM_SZ   (NSTAGE * STG_TOT)

template <int ACT, int OSPLIT>
__global__ void __launch_bounds__(256, 2) mmagemm_k(
    const __nv_bfloat16* __restrict__ Ah, const __nv_bfloat16* __restrict__ Al,
    const __nv_bfloat16* __restrict__ Bh, const __nv_bfloat16* __restrict__ Bl,
    const float* __restrict__ bias,
    float* __restrict__ Cf,
    __nv_bfloat16* __restrict__ Oh, __nv_bfloat16* __restrict__ Ol,
    int M, int N, int K)
{
    extern __shared__ char smem[];
    const uint32_t sbase = s2u(smem);
    const int tid = threadIdx.x;
    const int w = tid >> 5, lane = tid & 31;
    const int wm = w & 3, wn = w >> 2;
    const int row0 = blockIdx.y * 128, col0 = blockIdx.x * 128;
    const int kc = K >> 5;
    const int nc = 3 * kc;

    float acc[2][8][4];
#pragma unroll
    for (int i = 0; i < 2; i++)
#pragma unroll
        for (int j = 0; j < 8; j++)
#pragma unroll
            for (int q = 0; q < 4; q++) acc[i][j][q] = 0.f;

    auto load_chunk = [&](int c, int s) {
        int p = c / kc;
        int k0 = (c - p * kc) << 5;
        const __nv_bfloat16* Ab = (p == 2) ? Al : Ah;
        const __nv_bfloat16* Bb = (p == 1) ? Bl : Bh;
        uint32_t As = sbase + s * STG_TOT;
        uint32_t Bs = As + STG_A;
#pragma unroll
        for (int t = 0; t < 2; t++) {
            int si = tid + t * 256;
            int r = si >> 2, cc = si & 3;
            int gr = min(row0 + r, M - 1);
            cpasync16(As + r * 80 + cc * 16,
                      Ab + (size_t)gr * K + k0 + cc * 8);
            cpasync16(Bs + r * 80 + cc * 16,
                      Bb + (size_t)(col0 + r) * K + k0 + cc * 8);
        }
    };

    for (int s = 0; s < NSTAGE - 1; s++) {
        if (s < nc) load_chunk(s, s);
        cp_commit();
    }

    for (int c = 0; c < nc; c++) {
        cp_wait<NSTAGE - 2>();
        __syncthreads();

        int st = c & (NSTAGE - 1);
        uint32_t As = sbase + st * STG_TOT;
        uint32_t Bs = As + STG_A;

#pragma unroll
        for (int ko = 0; ko < 2; ko++) {
            uint32_t af[2][4];
#pragma unroll
            for (int mt = 0; mt < 2; mt++) {
                uint32_t addr = As + (wm * 32 + mt * 16 + (lane & 15)) * 80
                                + ko * 32 + ((lane >> 4) << 4);
                ldsm_x4(addr, af[mt][0], af[mt][1], af[mt][2], af[mt][3]);
            }
            uint32_t bf[8][2];
#pragma unroll
            for (int g = 0; g < 4; g++) {
                uint32_t nrow = wn * 64 + g * 16 + (lane & 7) + ((lane >> 4) << 3);
                uint32_t kb = ko * 32 + (((lane >> 3) & 1) << 4);
                uint32_t r0, r1, r2, r3;
                ldsm_x4(Bs + nrow * 80 + kb, r0, r1, r2, r3);
                bf[2 * g][0] = r0; bf[2 * g][1] = r1;
                bf[2 * g + 1][0] = r2; bf[2 * g + 1][1] = r3;
            }
#pragma unroll
            for (int mt = 0; mt < 2; mt++)
#pragma unroll
                for (int j = 0; j < 8; j++)
                    mma_bf16(acc[mt][j], af[mt], bf[j]);
        }
        __syncthreads();
        if (c + NSTAGE - 1 < nc)
            load_chunk(c + NSTAGE - 1, (c + NSTAGE - 1) & (NSTAGE - 1));
        cp_commit();
    }

    const int quad = lane >> 2, qlane = lane & 3;
#pragma unroll
    for (int mt = 0; mt < 2; mt++) {
#pragma unroll
        for (int half = 0; half < 2; half++) {
            int r = row0 + wm * 32 + mt * 16 + quad + half * 8;
            if (r >= M) continue;
#pragma unroll
            for (int j = 0; j < 8; j++) {
                int cidx = col0 + wn * 64 + j * 8 + qlane * 2;
                float v0 = acc[mt][j][2 * half]     + bias[cidx];
                float v1 = acc[mt][j][2 * half + 1] + bias[cidx + 1];
                if (ACT == 1) { v0 = gelu_f(v0); v1 = gelu_f(v1); }
                else if (ACT == 2) { v0 = fmaxf(v0, 0.f); v1 = fmaxf(v1, 0.f); }
                if (OSPLIT) {
                    __nv_bfloat16 h0 = __float2bfloat16(v0);
                    __nv_bfloat16 h1 = __float2bfloat16(v1);
                    __nv_bfloat16 l0 = __float2bfloat16(v0 - __bfloat162float(h0));
                    __nv_bfloat16 l1 = __float2bfloat16(v1 - __bfloat162float(h1));
                    *(__nv_bfloat162*)(Oh + (size_t)r * N + cidx) =
                        __halves2bfloat162(h0, h1);
                    *(__nv_bfloat162*)(Ol + (size_t)r * N + cidx) =
                        __halves2bfloat162(l0, l1);
                } else {
                    *(float2*)(Cf + (size_t)r * N + cidx) = make_float2(v0, v1);
                }
            }
        }
    }
}

// ---------------- CSR build kernels ----------------
__global__ void hist_k(const int* __restrict__ dst, int* __restrict__ deg, int E) {
    int e = blockIdx.x * blockDim.x + threadIdx.x;
    if (e < E) atomicAdd(&deg[dst[e]], 1);
}

__global__ void scanA_k(const int* __restrict__ deg, int* __restrict__ rowptr,
                        int* __restrict__ bsum, int n) {
    __shared__ int s[256];
    int i = blockIdx.x * 256 + threadIdx.x;
    int v = (i < n) ? deg[i] : 0;
    s[threadIdx.x] = v;
    __syncthreads();
#pragma unroll
    for (int off = 1; off < 256; off <<= 1) {
        int t = (threadIdx.x >= off) ? s[threadIdx.x - off] : 0;
        __syncthreads();
        s[threadIdx.x] += t;
        __syncthreads();
    }
    if (i < n) rowptr[i] = s[threadIdx.x] - v;
    if (threadIdx.x == 255) bsum[blockIdx.x] = s[255];
}

__global__ void scanB_k(int* __restrict__ bsum, int nb) {
    __shared__ int s[256];
    int v = (threadIdx.x < nb) ? bsum[threadIdx.x] : 0;
    s[threadIdx.x] = v;
    __syncthreads();
#pragma unroll
    for (int off = 1; off < 256; off <<= 1) {
        int t = (threadIdx.x >= off) ? s[threadIdx.x - off] : 0;
        __syncthreads();
        s[threadIdx.x] += t;
        __syncthreads();
    }
    if (threadIdx.x < nb) bsum[threadIdx.x] = s[threadIdx.x] - v;
}

__global__ void scanC_k(int* __restrict__ rowptr, int* __restrict__ cur,
                        const int* __restrict__ bsum, int n) {
    int i = blockIdx.x * blockDim.x + threadIdx.x;
    if (i < n) {
        int r = rowptr[i] + bsum[i >> 8];
        rowptr[i] = r;
        cur[i] = r;
    }
}

__global__ void fill_k(const int* __restrict__ src, const int* __restrict__ dst,
                       int* __restrict__ cur, int* __restrict__ eidx, int E) {
    int e = blockIdx.x * blockDim.x + threadIdx.x;
    if (e < E) {
        int p = atomicAdd(&cur[dst[e]], 1);
        eidx[p] = src[e];
    }
}

// ---------------- fused gather + bf16 split ----------------
__global__ void __launch_bounds__(256) gather_split_k(
    const float* __restrict__ xin, const int* __restrict__ rowptr,
    const int* __restrict__ deg, const int* __restrict__ eidx,
    __nv_bfloat162* __restrict__ hi, __nv_bfloat162* __restrict__ lo, int n)
{
    int node = blockIdx.x * 8 + (threadIdx.x >> 5);
    int lane = threadIdx.x & 31;
    if (node >= n) return;
    float4 a = ((const float4*)(xin + (size_t)node * 128))[lane];
    int beg = rowptr[node];
    int end = beg + deg[node];
    int j = beg;
    for (; j + 1 < end; j += 2) {
        int s0 = eidx[j], s1 = eidx[j + 1];
        float4 v0 = ((const float4*)(xin + (size_t)s0 * 128))[lane];
        float4 v1 = ((const float4*)(xin + (size_t)s1 * 128))[lane];
        a.x += v0.x + v1.x;
        a.y += v0.y + v1.y;
        a.z += v0.z + v1.z;
        a.w += v0.w + v1.w;
    }
    if (j < end) {
        int s0 = eidx[j];
        float4 v0 = ((const float4*)(xin + (size_t)s0 * 128))[lane];
        a.x += v0.x; a.y += v0.y; a.z += v0.z; a.w += v0.w;
    }
    __nv_bfloat16 hx = __float2bfloat16(a.x), hy = __float2bfloat16(a.y);
    __nv_bfloat16 hz = __float2bfloat16(a.z), hw = __float2bfloat16(a.w);
    size_t base = (size_t)node * 64 + lane * 2;
    hi[base]     = __halves2bfloat162(hx, hy);
    hi[base + 1] = __halves2bfloat162(hz, hw);
    lo[base]     = __halves2bfloat162(
        __float2bfloat16(a.x - __bfloat162float(hx)),
        __float2bfloat16(a.y - __bfloat162float(hy)));
    lo[base + 1] = __halves2bfloat162(
        __float2bfloat16(a.z - __bfloat162float(hz)),
        __float2bfloat16(a.w - __bfloat162float(hw)));
}

// ---------------- split / transpose-split ----------------
__global__ void split_k(const float4* __restrict__ in,
                        __nv_bfloat162* __restrict__ hi,
                        __nv_bfloat162* __restrict__ lo, int n4) {
    int i = blockIdx.x * blockDim.x + threadIdx.x;
    if (i >= n4) return;
    float4 v = in[i];
    __nv_bfloat16 hx = __float2bfloat16(v.x), hy = __float2bfloat16(v.y);
    __nv_bfloat16 hz = __float2bfloat16(v.z), hw = __float2bfloat16(v.w);
    hi[2 * i]     = __halves2bfloat162(hx, hy);
    hi[2 * i + 1] = __halves2bfloat162(hz, hw);
    lo[2 * i]     = __halves2bfloat162(
        __float2bfloat16(v.x - __bfloat162float(hx)),
        __float2bfloat16(v.y - __bfloat162float(hy)));
    lo[2 * i + 1] = __halves2bfloat162(
        __float2bfloat16(v.z - __bfloat162float(hz)),
        __float2bfloat16(v.w - __bfloat162float(hw)));
}

__global__ void splitT_k(const float* __restrict__ B,
                         __nv_bfloat16* __restrict__ th,
                         __nv_bfloat16* __restrict__ tl, int K, int N) {
    int idx = blockIdx.x * blockDim.x + threadIdx.x;
    if (idx >= K * N) return;
    int k = idx / N, n = idx - k * N;
    float v = B[idx];
    __nv_bfloat16 h = __float2bfloat16(v);
    th[(size_t)n * K + k] = h;
    tl[(size_t)n * K + k] = __float2bfloat16(v - __bfloat162float(h));
}

// ---------------- misc kernels ----------------
__global__ void zero_k(float* __restrict__ p, int n) {
    int i = blockIdx.x * blockDim.x + threadIdx.x;
    if (i < n) p[i] = 0.f;
}

__global__ void stats_k(const float* __restrict__ A, float* __restrict__ st,
                        int M, int C, int rowsPerBlock) {
    int c = threadIdx.x;
    int r0 = blockIdx.x * rowsPerBlock;
    int r1 = min(r0 + rowsPerBlock, M);
    float s = 0.f, q = 0.f;
    for (int r = r0; r < r1; r++) {
        float v = A[(size_t)r * C + c];
        s += v;
        q = fmaf(v, v, q);
    }
    atomicAdd(&st[c], s);
    atomicAdd(&st[C + c], q);
}

__global__ void bnfin_k(float* __restrict__ st, const float* __restrict__ g,
                        const float* __restrict__ b, int C, float invN) {
    int c = blockIdx.x * blockDim.x + threadIdx.x;
    if (c >= C) return;
    float mu  = st[c] * invN;
    float var = st[C + c] * invN - mu * mu;
    float sc  = g[c] * rsqrtf(var + 1e-5f);
    st[c]     = sc;
    st[C + c] = b[c] - mu * sc;
}

__global__ void bnpool_k(const float* __restrict__ pre, const float* __restrict__ st,
                         const int* __restrict__ batch, float* __restrict__ hout,
                         float* __restrict__ pool, int M, int C, int poolOff) {
    int i = blockIdx.x * blockDim.x + threadIdx.x;
    int c4cnt = C >> 2;
    int r = i / c4cnt;
    if (r >= M) return;
    int c = (i - r * c4cnt) << 2;
    float4 v  = *(const float4*)(pre + (size_t)r * C + c);
    float4 sc = *(const float4*)(st + c);
    float4 sh = *(const float4*)(st + C + c);
    float o0 = gelu_f(fmaf(v.x, sc.x, sh.x));
    float o1 = gelu_f(fmaf(v.y, sc.y, sh.y));
    float o2 = gelu_f(fmaf(v.z, sc.z, sh.z));
    float o3 = gelu_f(fmaf(v.w, sc.w, sh.w));
    if (hout) *(float4*)(hout + (size_t)r * C + c) = make_float4(o0, o1, o2, o3);
    int gidx = batch[r];
    float* p = pool + (size_t)gidx * POOLW + poolOff + c;
    atomicAdd(p + 0, o0);
    atomicAdd(p + 1, o1);
    atomicAdd(p + 2, o2);
    atomicAdd(p + 3, o3);
}

// ---------------- host launch ----------------
template <int ACT, int OSPLIT>
static void run_gemm(const __nv_bfloat16* Ah, const __nv_bfloat16* Al,
                     const __nv_bfloat16* Bh, const __nv_bfloat16* Bl,
                     const float* bias, float* Cf,
                     __nv_bfloat16* Oh, __nv_bfloat16* Ol,
                     int M, int N, int K) {
    cudaFuncSetAttribute(mmagemm_k<ACT, OSPLIT>,
                         cudaFuncAttributeMaxDynamicSharedMemorySize, SMEM_SZ);
    dim3 grid(N / 128, (M + 127) / 128);
    mmagemm_k<ACT, OSPLIT><<<grid, 256, SMEM_SZ>>>(Ah, Al, Bh, Bl, bias, Cf,
                                                   Oh, Ol, M, N, K);
}

extern "C" void kernel_launch(void* const* d_in, const int* in_sizes, int n_in,
                              void* d_out, int out_size) {
    const float* x     = (const float*)d_in[0];
    const int*   ei    = (const int*)d_in[1];
    const int*   batch = (const int*)d_in[2];
    const float* c1W1 = (const float*)d_in[3];
    const float* c1b1 = (const float*)d_in[4];
    const float* c1W2 = (const float*)d_in[5];
    const float* c1b2 = (const float*)d_in[6];
    const float* bn1g = (const float*)d_in[7];
    const float* bn1b = (const float*)d_in[8];
    const float* c2W1 = (const float*)d_in[9];
    const float* c2b1 = (const float*)d_in[10];
    const float* c2W2 = (const float*)d_in[11];
    const float* c2b2 = (const float*)d_in[12];
    const float* bn2g = (const float*)d_in[13];
    const float* bn2b = (const float*)d_in[14];
    const float* c3W1 = (const float*)d_in[15];
    const float* c3b1 = (const float*)d_in[16];
    const float* c3W2 = (const float*)d_in[17];
    const float* c3b2 = (const float*)d_in[18];
    const float* bn3g = (const float*)d_in[19];
    const float* bn3b = (const float*)d_in[20];
    const float* l1W  = (const float*)d_in[21];
    const float* l1b  = (const float*)d_in[22];
    const float* l2W  = (const float*)d_in[23];
    const float* l2b  = (const float*)d_in[24];
    float* out = (float*)d_out;

    const int* srcp = ei;
    const int* dstp = ei + NEDGES;

    float *pre, *h1, *h2, *pool, *s1, *s2, *s3;
    int *deg, *rowptr, *cur, *eidx, *bsum;
    __nv_bfloat16 *sah, *sal, *smh, *sml, *wh, *wl;
    cudaGetSymbolAddress((void**)&pre,    g_pre);
    cudaGetSymbolAddress((void**)&h1,     g_h1);
    cudaGetSymbolAddress((void**)&h2,     g_h2);
    cudaGetSymbolAddress((void**)&pool,   g_pool);
    cudaGetSymbolAddress((void**)&s1,     g_st1);
    cudaGetSymbolAddress((void**)&s2,     g_st2);
    cudaGetSymbolAddress((void**)&s3,     g_st3);
    cudaGetSymbolAddress((void**)&deg,    g_deg);
    cudaGetSymbolAddress((void**)&rowptr, g_rowptr);
    cudaGetSymbolAddress((void**)&cur,    g_cur);
    cudaGetSymbolAddress((void**)&eidx,   g_eidx);
    cudaGetSymbolAddress((void**)&bsum,   g_bsum);
    cudaGetSymbolAddress((void**)&sah,    g_sa_h);
    cudaGetSymbolAddress((void**)&sal,    g_sa_l);
    cudaGetSymbolAddress((void**)&smh,    g_sm_h);
    cudaGetSymbolAddress((void**)&sml,    g_sm_l);
    cudaGetSymbolAddress((void**)&wh,     g_w_h);
    cudaGetSymbolAddress((void**)&wl,     g_w_l);

    const float invN = 1.0f / (float)NNODES;
    const int statsBlocks = (NNODES + 255) / 256;
    const int bn128Blocks = (NNODES * DH / 4 + 255) / 256;
    const int bn512Blocks = (NNODES * DHL / 4 + 255) / 256;
    const int gatherBlocks = (NNODES + 7) / 8;
    const int scanBlocks = (NNODES + 255) / 256;   // 196
    const int eBlocks = (NEDGES + 255) / 256;

    // zero pooled + stats accumulators + degree histogram
    zero_k<<<(NG * POOLW + 255) / 256, 256>>>(pool, NG * POOLW);
    zero_k<<<1, 256>>>(s1, 2 * DH);
    zero_k<<<1, 256>>>(s2, 2 * DH);
    zero_k<<<4, 256>>>(s3, 2 * DHL);
    zero_k<<<scanBlocks, 256>>>((float*)deg, NNODES);

    // ---- build CSR (dst-sorted edge list) ----
    hist_k<<<eBlocks, 256>>>(dstp, deg, NEDGES);
    scanA_k<<<scanBlocks, 256>>>(deg, rowptr, bsum, NNODES);
    scanB_k<<<1, 256>>>(bsum, scanBlocks);
    scanC_k<<<scanBlocks, 256>>>(rowptr, cur, bsum, NNODES);
    fill_k<<<eBlocks, 256>>>(srcp, dstp, cur, eidx, NEDGES);

    // split+transpose all weights to [N,K] bf16 hi/lo
    splitT_k<<<(128 * 128 + 255) / 256, 256>>>(c1W1, wh + OFF_C1W1, wl + OFF_C1W1, 128, 128);
    splitT_k<<<(128 * 128 + 255) / 256, 256>>>(c1W2, wh + OFF_C1W2, wl + OFF_C1W2, 128, 128);
    splitT_k<<<(128 * 128 + 255) / 256, 256>>>(c2W1, wh + OFF_C2W1, wl + OFF_C2W1, 128, 128);
    splitT_k<<<(128 * 128 + 255) / 256, 256>>>(c2W2, wh + OFF_C2W2, wl + OFF_C2W2, 128, 128);
    splitT_k<<<(128 * 512 + 255) / 256, 256>>>(c3W1, wh + OFF_C3W1, wl + OFF_C3W1, 128, 512);
    splitT_k<<<(512 * 512 + 255) / 256, 256>>>(c3W2, wh + OFF_C3W2, wl + OFF_C3W2, 512, 512);
    splitT_k<<<(768 * 1024 + 255) / 256, 256>>>(l1W, wh + OFF_L1W, wl + OFF_L1W, 768, 1024);
    splitT_k<<<(1024 * 512 + 255) / 256, 256>>>(l2W, wh + OFF_L2W, wl + OFF_L2W, 1024, 512);

    // -------- layer 1 --------
    gather_split_k<<<gatherBlocks, 256>>>(x, rowptr, deg, eidx,
                                          (__nv_bfloat162*)sah, (__nv_bfloat162*)sal, NNODES);
    run_gemm<1, 1>(sah, sal, wh + OFF_C1W1, wl + OFF_C1W1, c1b1,
                   nullptr, smh, sml, NNODES, DH, DH);
    run_gemm<0, 0>(smh, sml, wh + OFF_C1W2, wl + OFF_C1W2, c1b2,
                   pre, nullptr, nullptr, NNODES, DH, DH);
    stats_k<<<statsBlocks, DH>>>(pre, s1, NNODES, DH, 256);
    bnfin_k<<<1, DH>>>(s1, bn1g, bn1b, DH, invN);
    bnpool_k<<<bn128Blocks, 256>>>(pre, s1, batch, h1, pool, NNODES, DH, 0);

    // -------- layer 2 --------
    gather_split_k<<<gatherBlocks, 256>>>(h1, rowptr, deg, eidx,
                                          (__nv_bfloat162*)sah, (__nv_bfloat162*)sal, NNODES);
    run_gemm<1, 1>(sah, sal, wh + OFF_C2W1, wl + OFF_C2W1, c2b1,
                   nullptr, smh, sml, NNODES, DH, DH);
    run_gemm<0, 0>(smh, sml, wh + OFF_C2W2, wl + OFF_C2W2, c2b2,
                   pre, nullptr, nullptr, NNODES, DH, DH);
    stats_k<<<statsBlocks, DH>>>(pre, s2, NNODES, DH, 256);
    bnfin_k<<<1, DH>>>(s2, bn2g, bn2b, DH, invN);
    bnpool_k<<<bn128Blocks, 256>>>(pre, s2, batch, h2, pool, NNODES, DH, DH);

    // -------- layer 3 --------
    gather_split_k<<<gatherBlocks, 256>>>(h2, rowptr, deg, eidx,
                                          (__nv_bfloat162*)sah, (__nv_bfloat162*)sal, NNODES);
    run_gemm<1, 1>(sah, sal, wh + OFF_C3W1, wl + OFF_C3W1, c3b1,
                   nullptr, smh, sml, NNODES, DHL, DH);
    run_gemm<0, 0>(smh, sml, wh + OFF_C3W2, wl + OFF_C3W2, c3b2,
                   pre, nullptr, nullptr, NNODES, DHL, DHL);
    stats_k<<<statsBlocks, DHL>>>(pre, s3, NNODES, DHL, 256);
    bnfin_k<<<4, DHL / 4>>>(s3, bn3g, bn3b, DHL, invN);
    bnpool_k<<<bn512Blocks, 256>>>(pre, s3, batch, nullptr, pool, NNODES, DHL, 2 * DH);

    // -------- head --------
    split_k<<<(NG * POOLW / 4 + 255) / 256, 256>>>((const float4*)pool,
                                                   (__nv_bfloat162*)sah,
                                                   (__nv_bfloat162*)sal, NG * POOLW / 4);
    run_gemm<2, 1>(sah, sal, wh + OFF_L1W, wl + OFF_L1W, l1b,
                   nullptr, smh, sml, NG, 1024, POOLW);
    run_gemm<0, 0>(smh, sml, wh + OFF_L2W, wl + OFF_L2W, l2b,
                   out, nullptr, nullptr, NG, NC, 1024);
}